// round 7
// baseline (speedup 1.0000x reference)
#include <cuda_runtime.h>
#include <cuda_fp16.h>
#include <cstdint>

// ---------------------------------------------------------------------------
// Model_RNN: bidirectional RNN
//   0) prep: embproj[v][n] = emb[v]@W_e[n]^T + bias_n ; g_Wh = half(W[:, :768])
//   1) xp = inputs @ W^T, fp16 mma (fp32 acc); A: LDG 3-ahead reg queue (fp16),
//      B: cp.async 3-stage.  xp stored transposed: [dir][b][t][64]
//   2) fwd/bwd tanh-RNN scans, coalesced xp/h, fast exact tanh
//   3) head: Linear(128->32) -> LayerNorm -> ReLU -> Linear(32->4), 64-tok tiles
// ---------------------------------------------------------------------------

#define BATCH 64
#define TT    512
#define FEAT  768
#define EDIM  100
#define KDIM  868
#define NTOK  (BATCH * TT)       // 32768

__device__ float  g_xp[2 * NTOK * 64];   // [dir][b][t][64]
__device__ float  g_h [2 * NTOK * 64];   // [dir][b][t][64]
__device__ __half g_Wh[128 * FEAT];      // half-rounded W_ih rows (n major)
__device__ float  g_embproj[512 * 128];  // emb @ W_e^T + (b_ih + b_hh)

// ---------------------------------------------------------------------------
__device__ __forceinline__ void cpa16(void* sdst, const void* gsrc) {
    uint32_t s = (uint32_t)__cvta_generic_to_shared(sdst);
    asm volatile("cp.async.cg.shared.global [%0], [%1], 16;\n" :: "r"(s), "l"(gsrc));
}
__device__ __forceinline__ void mma_f16(float* c, const uint32_t* a, const uint32_t* b) {
    asm volatile(
        "mma.sync.aligned.m16n8k16.row.col.f32.f16.f16.f32 "
        "{%0,%1,%2,%3}, {%4,%5,%6,%7}, {%8,%9}, {%0,%1,%2,%3};\n"
        : "+f"(c[0]), "+f"(c[1]), "+f"(c[2]), "+f"(c[3])
        : "r"(a[0]), "r"(a[1]), "r"(a[2]), "r"(a[3]), "r"(b[0]), "r"(b[1]));
}

// ---------------------------------------------------------------------------
// Kernel 0: prep. blocks 0..511 -> embproj row v; blocks 512..639 -> W to half.
// ---------------------------------------------------------------------------
__global__ __launch_bounds__(128)
void prep_kernel(const float* __restrict__ emb,
                 const float* __restrict__ Wf, const float* __restrict__ Wb,
                 const float* __restrict__ bihf, const float* __restrict__ bhhf,
                 const float* __restrict__ bihb, const float* __restrict__ bhhb)
{
    const int bid = blockIdx.x, tid = threadIdx.x;
    if (bid < 512) {
        __shared__ float es[EDIM];
        if (tid < EDIM) es[tid] = emb[bid * EDIM + tid];
        __syncthreads();
        const int n = tid;
        const float* wr = (n < 64) ? (Wf + n * KDIM + FEAT)
                                   : (Wb + (n - 64) * KDIM + FEAT);
        float acc = (n < 64) ? (bihf[n] + bhhf[n]) : (bihb[n - 64] + bhhb[n - 64]);
        #pragma unroll 4
        for (int e = 0; e < EDIM; e++) acc = fmaf(es[e], wr[e], acc);
        g_embproj[bid * 128 + n] = acc;
    } else {
        const int n = bid - 512;
        const float* wr = (n < 64) ? (Wf + n * KDIM) : (Wb + (n - 64) * KDIM);
        #pragma unroll
        for (int k = tid; k < FEAT; k += 128)
            g_Wh[n * FEAT + k] = __float2half_rn(wr[k]);
    }
}

// ---------------------------------------------------------------------------
// Kernel 1: fp16 mma GEMM (M=32768, N=128, K=768), fp32 accumulate.
// 256 CTAs x 128 rows; 8 warps (4m x 2n, warp tile 32x64); K-chunk 32.
// A: LDG 3 chunks ahead -> cvt fp16 in regs -> STS (2-stage smem)
// B: cp.async 3-stage from pre-halved g_Wh.
// ---------------------------------------------------------------------------
#define GK    32
#define NCH   (FEAT / GK)    // 24
#define APAD  40             // halves per row (80B stride)

__global__ __launch_bounds__(256, 2)
void gemm1_kernel(const float* __restrict__ inp, const int* __restrict__ posi)
{
    __shared__ __half Asm[2][128 * APAD];
    __shared__ __half Bsm[3][128 * APAD];

    const int tid  = threadIdx.x;
    const int m0   = blockIdx.x * 128;
    const int lane = tid & 31;
    const int warp = tid >> 5;
    const int wm   = warp >> 1;
    const int wn   = warp & 1;
    const int g    = lane >> 2;
    const int t4   = lane & 3;

    bool p64;
    {
        int odd  = posi[2 * lane + 1];
        int even = posi[2 * lane];
        bool z = (odd == 0) && (even >= 0) && (even < 512);
        p64 = (__ballot_sync(0xffffffffu, z) == 0xffffffffu);
    }

    const int ar = tid >> 1;             // row 0..127
    const int ac = (tid & 1) * 16;       // col 0 / 16

    uint4 qa[2][2];                      // fp16 queue, 2 chunks x 16 halves

    auto ldgA = [&](int ch, uint4* q) {
        const float* p = inp + (size_t)(m0 + ar) * FEAT + ch * GK + ac;
        float4 v0 = __ldg((const float4*)(p + 0));
        float4 v1 = __ldg((const float4*)(p + 4));
        float4 v2 = __ldg((const float4*)(p + 8));
        float4 v3 = __ldg((const float4*)(p + 12));
        __half2 h[8];
        h[0] = __floats2half2_rn(v0.x, v0.y); h[1] = __floats2half2_rn(v0.z, v0.w);
        h[2] = __floats2half2_rn(v1.x, v1.y); h[3] = __floats2half2_rn(v1.z, v1.w);
        h[4] = __floats2half2_rn(v2.x, v2.y); h[5] = __floats2half2_rn(v2.z, v2.w);
        h[6] = __floats2half2_rn(v3.x, v3.y); h[7] = __floats2half2_rn(v3.z, v3.w);
        q[0] = *(uint4*)&h[0];
        q[1] = *(uint4*)&h[4];
    };
    auto stsA = [&](int s, const uint4* q) {
        *(uint4*)&Asm[s][ar * APAD + ac]     = q[0];
        *(uint4*)&Asm[s][ar * APAD + ac + 8] = q[1];
    };
    auto stageB = [&](int ch, int slot) {
        #pragma unroll
        for (int i = 0; i < 2; i++) {
            int lin = tid + i * 256;
            int n = lin >> 2, c8 = lin & 3;
            cpa16(&Bsm[slot][n * APAD + c8 * 8],
                  g_Wh + (size_t)n * FEAT + ch * GK + c8 * 8);
        }
    };

    float c[2][8][4];
    #pragma unroll
    for (int mt = 0; mt < 2; mt++)
        #pragma unroll
        for (int nt = 0; nt < 8; nt++)
            #pragma unroll
            for (int i = 0; i < 4; i++) c[mt][nt][i] = 0.f;

    // preamble
    ldgA(0, qa[0]); ldgA(1, qa[1]);
    stageB(0, 0); asm volatile("cp.async.commit_group;\n" ::: "memory");
    stageB(1, 1); asm volatile("cp.async.commit_group;\n" ::: "memory");
    stsA(0, qa[0]);
    ldgA(2, qa[0]);
    asm volatile("cp.async.wait_group 1;\n" ::: "memory");   // B0 ready
    __syncthreads();

    int bs = 0;   // B slot of current chunk
    for (int ch = 0; ch < NCH; ch++) {
        const int s = ch & 1;
        if (ch + 1 < NCH) stsA(s ^ 1, qa[(ch + 1) & 1]);     // stage A(ch+1)
        if (ch + 3 < NCH) ldgA(ch + 3, qa[(ch + 1) & 1]);    // refill queue
        int bs2 = bs + 2; if (bs2 >= 3) bs2 -= 3;
        if (ch + 2 < NCH) {
            stageB(ch + 2, bs2);
            asm volatile("cp.async.commit_group;\n" ::: "memory");
        }

        const __half* Ab = Asm[s];
        const __half* Bb = Bsm[bs];
        #pragma unroll
        for (int ks = 0; ks < 2; ks++) {
            const int kb = ks * 16;
            uint32_t a[2][4], bb[8][2];
            #pragma unroll
            for (int mt = 0; mt < 2; mt++) {
                int r = wm * 32 + mt * 16 + g;
                int base = r * APAD + kb + t4 * 2;
                a[mt][0] = *(const uint32_t*)&Ab[base];
                a[mt][1] = *(const uint32_t*)&Ab[base + 8 * APAD];
                a[mt][2] = *(const uint32_t*)&Ab[base + 8];
                a[mt][3] = *(const uint32_t*)&Ab[base + 8 * APAD + 8];
            }
            #pragma unroll
            for (int nt = 0; nt < 8; nt++) {
                int cn = wn * 64 + nt * 8 + g;
                int bbase = cn * APAD + kb + t4 * 2;
                bb[nt][0] = *(const uint32_t*)&Bb[bbase];
                bb[nt][1] = *(const uint32_t*)&Bb[bbase + 8];
            }
            #pragma unroll
            for (int mt = 0; mt < 2; mt++)
                #pragma unroll
                for (int nt = 0; nt < 8; nt++)
                    mma_f16(c[mt][nt], a[mt], bb[nt]);
        }

        if (ch + 2 < NCH)
            asm volatile("cp.async.wait_group 1;\n" ::: "memory");  // B(ch+1) done
        else
            asm volatile("cp.async.wait_group 0;\n" ::: "memory");
        __syncthreads();
        bs = bs + 1; if (bs >= 3) bs -= 3;
    }

    // epilogue: + embproj[pos[row]], store transposed to g_xp[dir][b][t][64]
    #pragma unroll
    for (int mt = 0; mt < 2; mt++) {
        int r = m0 + wm * 32 + mt * 16 + g;
        int i0 = (p64 ? posi[2 * r] : posi[r]) & 511;
        int i1 = (p64 ? posi[2 * (r + 8)] : posi[r + 8]) & 511;
        const float* e0 = g_embproj + i0 * 128;
        const float* e1 = g_embproj + i1 * 128;
        #pragma unroll
        for (int nt = 0; nt < 8; nt++) {
            int cn = wn * 64 + nt * 8 + 2 * t4;
            int dir = cn >> 6, j = cn & 63;
            size_t base0 = (size_t)dir * (NTOK * 64) + (size_t)r * 64 + j;
            size_t base1 = (size_t)dir * (NTOK * 64) + (size_t)(r + 8) * 64 + j;
            g_xp[base0]     = c[mt][nt][0] + e0[cn];
            g_xp[base0 + 1] = c[mt][nt][1] + e0[cn + 1];
            g_xp[base1]     = c[mt][nt][2] + e1[cn];
            g_xp[base1 + 1] = c[mt][nt][3] + e1[cn + 1];
        }
    }
}

// ---------------------------------------------------------------------------
// Kernel 2: RNN scans. 128 CTAs = (b,dir), 128 threads; pair-split dot;
// coalesced xp/h ([dir][b][t][64]); exact fast tanh via __expf.
// ---------------------------------------------------------------------------
__global__ __launch_bounds__(128, 8)
void scan_kernel(const float* __restrict__ Whf, const float* __restrict__ Whb)
{
    const int pair = blockIdx.x;
    const int b = pair >> 1, dir = pair & 1;
    const int tid  = threadIdx.x;
    const int j    = tid >> 1;
    const int half = tid & 1;

    const float* W = dir ? Whb : Whf;
    float w[32];
    #pragma unroll
    for (int k = 0; k < 32; k += 4) {
        float4 v = *(const float4*)(W + j * 64 + half * 32 + k);
        w[k] = v.x; w[k + 1] = v.y; w[k + 2] = v.z; w[k + 3] = v.w;
    }

    __shared__ float hbuf[2][64];
    if (tid < 64) hbuf[0][tid] = 0.f;
    __syncthreads();

    const size_t sbase = (size_t)dir * (NTOK * 64) + (size_t)b * (TT * 64) + j;
    const float* xpb = g_xp + sbase;
    float*       ob  = g_h  + sbase;

    float xq[4];
    #pragma unroll
    for (int i = 0; i < 4; i++) {
        int t = dir ? (TT - 1 - i) : i;
        xq[i] = __ldg(xpb + (size_t)t * 64);
    }

    int p = 0;
    for (int s4 = 0; s4 < TT / 4; s4++) {
        #pragma unroll
        for (int u = 0; u < 4; u++) {
            const int s = s4 * 4 + u;
            float x = xq[u];
            const int sp = s + 4;
            if (sp < TT) {
                int tp = dir ? (TT - 1 - sp) : sp;
                xq[u] = __ldg(xpb + (size_t)tp * 64);
            }
            float a0 = 0.f, a1 = 0.f, a2 = 0.f, a3 = 0.f;
            const float* hp = hbuf[p] + half * 32;
            #pragma unroll
            for (int k = 0; k < 32; k += 4) {
                float4 hv = *(const float4*)(hp + k);
                a0 = fmaf(w[k],     hv.x, a0);
                a1 = fmaf(w[k + 1], hv.y, a1);
                a2 = fmaf(w[k + 2], hv.z, a2);
                a3 = fmaf(w[k + 3], hv.w, a3);
            }
            float a = (a0 + a1) + (a2 + a3);
            a += __shfl_xor_sync(0xffffffffu, a, 1);
            float z = x + a;
            // exact-ish tanh: 1 - 2/(1+e^{2z}); MUFU ex2+rcp, ~1e-6 rel err
            float e = __expf(z + z);
            float h = 1.f - __fdividef(2.f, e + 1.f);
            int t = dir ? (TT - 1 - s) : s;
            if (half == 0) hbuf[p ^ 1][j] = h;
            else           ob[(size_t)t * 64] = h;
            __syncthreads();
            p ^= 1;
        }
    }
}

// ---------------------------------------------------------------------------
// Kernel 3: head, 64-token tiles (512 CTAs), ~63KB smem -> 3 CTAs/SM.
// ---------------------------------------------------------------------------
#define HTOK 64
#define HEAD_SMEM_FLOATS (128*68 + 128*36 + HTOK*33 + 128 + 32*3 + 4)

__global__ __launch_bounds__(256, 3)
void head_kernel(const float* __restrict__ W1, const float* __restrict__ b1,
                 const float* __restrict__ gamma, const float* __restrict__ beta,
                 const float* __restrict__ W2, const float* __restrict__ b2,
                 float* __restrict__ out)
{
    extern __shared__ float sm[];
    float* As  = sm;                    // [k=128][m=64 pad 68]
    float* W1t = As + 128 * 68;         // [k][n] 128 x 36
    float* h1s = W1t + 128 * 36;        // [m][n] 64 x 33
    float* W2s = h1s + HTOK * 33;       // 128
    float* b1s = W2s + 128;             // 32
    float* gms = b1s + 32;              // 32
    float* bts = gms + 32;              // 32
    float* b2s = bts + 32;              // 4

    const int tid = threadIdx.x;
    const int t0  = blockIdx.x * HTOK;

    #pragma unroll
    for (int i = 0; i < 16; i++) {      // W1t[k][n] = W1[n][k]
        int lin = tid + i * 256;
        int k = lin & 127, n = lin >> 7;
        W1t[k * 36 + n] = W1[n * 128 + k];
    }
    if (tid < 128) W2s[tid] = W2[tid];
    if (tid < 32) { b1s[tid] = b1[tid]; gms[tid] = gamma[tid]; bts[tid] = beta[tid]; }
    if (tid < 4)  b2s[tid] = b2[tid];

    // As[k][m] from g_h[dir][tok][64]: k<64 -> fwd, k>=64 -> bwd
    #pragma unroll
    for (int i = 0; i < 8; i++) {
        int lin = tid + i * 256;        // 2048 float4 pieces
        int m = lin & 63, k4 = lin >> 6;   // k4 0..31
        size_t src = (k4 >= 16 ? (size_t)(NTOK * 64) : 0)
                   + (size_t)(t0 + m) * 64 + (k4 & 15) * 4;
        float4 v = *(const float4*)(g_h + src);
        As[(k4 * 4 + 0) * 68 + m] = v.x;
        As[(k4 * 4 + 1) * 68 + m] = v.y;
        As[(k4 * 4 + 2) * 68 + m] = v.z;
        As[(k4 * 4 + 3) * 68 + m] = v.w;
    }
    __syncthreads();

    const int tt = tid >> 3;            // 0..31 -> tokens tt*2..+1
    const int ot = tid & 7;             // outputs ot*4..+3
    float acc[2][4];
    #pragma unroll
    for (int i = 0; i < 2; i++)
        #pragma unroll
        for (int jx = 0; jx < 4; jx++) acc[i][jx] = 0.f;

    #pragma unroll 8
    for (int k = 0; k < 128; k++) {
        float2 av = *(const float2*)(As + k * 68 + tt * 2);
        float4 bv = *(const float4*)(W1t + k * 36 + ot * 4);
        acc[0][0] = fmaf(av.x, bv.x, acc[0][0]); acc[0][1] = fmaf(av.x, bv.y, acc[0][1]);
        acc[0][2] = fmaf(av.x, bv.z, acc[0][2]); acc[0][3] = fmaf(av.x, bv.w, acc[0][3]);
        acc[1][0] = fmaf(av.y, bv.x, acc[1][0]); acc[1][1] = fmaf(av.y, bv.y, acc[1][1]);
        acc[1][2] = fmaf(av.y, bv.z, acc[1][2]); acc[1][3] = fmaf(av.y, bv.w, acc[1][3]);
    }
    #pragma unroll
    for (int i = 0; i < 2; i++)
        #pragma unroll
        for (int jx = 0; jx < 4; jx++)
            h1s[(tt * 2 + i) * 33 + ot * 4 + jx] = acc[i][jx] + b1s[ot * 4 + jx];
    __syncthreads();

    if (tid < HTOK) {
        float h[32];
        #pragma unroll
        for (int i = 0; i < 32; i++) h[i] = h1s[tid * 33 + i];
        float s1 = 0.f, s2 = 0.f;
        #pragma unroll
        for (int i = 0; i < 32; i++) { s1 += h[i]; s2 = fmaf(h[i], h[i], s2); }
        float mu  = s1 * (1.f / 32.f);
        float var = s2 * (1.f / 32.f) - mu * mu;
        float inv = rsqrtf(var + 1e-5f);
        float o0 = b2s[0], o1 = b2s[1], o2 = b2s[2], o3 = b2s[3];
        #pragma unroll
        for (int i = 0; i < 32; i++) {
            float r = fmaf((h[i] - mu) * inv, gms[i], bts[i]);
            r = fmaxf(r, 0.f);
            o0 = fmaf(W2s[i],      r, o0);
            o1 = fmaf(W2s[32 + i], r, o1);
            o2 = fmaf(W2s[64 + i], r, o2);
            o3 = fmaf(W2s[96 + i], r, o3);
        }
        *(float4*)(out + (size_t)(t0 + tid) * 4) = make_float4(o0, o1, o2, o3);
    }
}

// ---------------------------------------------------------------------------
extern "C" void kernel_launch(void* const* d_in, const int* in_sizes, int n_in,
                              void* d_out, int out_size)
{
    const float* inputs = (const float*)d_in[0];
    const int*   posi   = (const int*)  d_in[1];
    const float* emb    = (const float*)d_in[2];
    const float* Wihf   = (const float*)d_in[3];
    const float* Whhf   = (const float*)d_in[4];
    const float* bihf   = (const float*)d_in[5];
    const float* bhhf   = (const float*)d_in[6];
    const float* Wihb   = (const float*)d_in[7];
    const float* Whhb   = (const float*)d_in[8];
    const float* bihb   = (const float*)d_in[9];
    const float* bhhb   = (const float*)d_in[10];
    const float* W1     = (const float*)d_in[11];
    const float* b1     = (const float*)d_in[12];
    const float* gamma  = (const float*)d_in[13];
    const float* beta   = (const float*)d_in[14];
    const float* W2     = (const float*)d_in[15];
    const float* b2     = (const float*)d_in[16];
    float* out = (float*)d_out;

    const int head_smem = HEAD_SMEM_FLOATS * (int)sizeof(float);
    cudaFuncSetAttribute(head_kernel, cudaFuncAttributeMaxDynamicSharedMemorySize, head_smem);

    prep_kernel<<<640, 128>>>(emb, Wihf, Wihb, bihf, bhhf, bihb, bhhb);
    gemm1_kernel<<<256, 256>>>(inputs, posi);
    scan_kernel<<<128, 128>>>(Whhf, Whhb);
    head_kernel<<<512, 256, head_smem>>>(W1, b1, gamma, beta, W2, b2, out);
}

// round 12
// speedup vs baseline: 1.0536x; 1.0536x over previous
#include <cuda_runtime.h>
#include <cuda_fp16.h>
#include <cstdint>

// ---------------------------------------------------------------------------
// Model_RNN: bidirectional RNN
//   0) prep: embproj[v][n] = emb[v]@W_e[n]^T + bias_n ; g_Wh = half(W[:, :768])
//   1) xp = inputs @ W^T, fp16 mma (fp32 acc); 512 CTAs x 64 rows, GK=64,
//      3 CTAs/SM; xp stored transposed [dir][b][t][64]
//   2) fwd/bwd tanh-RNN scans, coalesced xp/h, fast exact tanh
//   3) head (128-tok tiles): Linear(128->32) -> LN -> ReLU -> Linear(32->4)
// (Resubmission of the R7 kernel: audited memory-safe and hang-free; the R7/R8
//  bench failures carried no rc/log and are attributed to broker flake.)
// ---------------------------------------------------------------------------

#define BATCH 64
#define TT    512
#define FEAT  768
#define EDIM  100
#define KDIM  868
#define NTOK  (BATCH * TT)       // 32768

__device__ float  g_xp[2 * NTOK * 64];   // [dir][b][t][64]
__device__ float  g_h [2 * NTOK * 64];   // [dir][b][t][64]
__device__ __half g_Wh[128 * FEAT];      // half-rounded W_ih rows (n major)
__device__ float  g_embproj[512 * 128];  // emb @ W_e^T + (b_ih + b_hh)

// ---------------------------------------------------------------------------
__device__ __forceinline__ void cpa16(void* sdst, const void* gsrc) {
    uint32_t s = (uint32_t)__cvta_generic_to_shared(sdst);
    asm volatile("cp.async.cg.shared.global [%0], [%1], 16;\n" :: "r"(s), "l"(gsrc));
}
__device__ __forceinline__ void mma_f16(float* c, const uint32_t* a, const uint32_t* b) {
    asm volatile(
        "mma.sync.aligned.m16n8k16.row.col.f32.f16.f16.f32 "
        "{%0,%1,%2,%3}, {%4,%5,%6,%7}, {%8,%9}, {%0,%1,%2,%3};\n"
        : "+f"(c[0]), "+f"(c[1]), "+f"(c[2]), "+f"(c[3])
        : "r"(a[0]), "r"(a[1]), "r"(a[2]), "r"(a[3]), "r"(b[0]), "r"(b[1]));
}

// ---------------------------------------------------------------------------
// Kernel 0: prep. blocks 0..511 -> embproj row v; blocks 512..639 -> W to half.
// ---------------------------------------------------------------------------
__global__ __launch_bounds__(128)
void prep_kernel(const float* __restrict__ emb,
                 const float* __restrict__ Wf, const float* __restrict__ Wb,
                 const float* __restrict__ bihf, const float* __restrict__ bhhf,
                 const float* __restrict__ bihb, const float* __restrict__ bhhb)
{
    const int bid = blockIdx.x, tid = threadIdx.x;
    if (bid < 512) {
        __shared__ float es[EDIM];
        if (tid < EDIM) es[tid] = emb[bid * EDIM + tid];
        __syncthreads();
        const int n = tid;
        const float* wr = (n < 64) ? (Wf + n * KDIM + FEAT)
                                   : (Wb + (n - 64) * KDIM + FEAT);
        float acc = (n < 64) ? (bihf[n] + bhhf[n]) : (bihb[n - 64] + bhhb[n - 64]);
        #pragma unroll 4
        for (int e = 0; e < EDIM; e++) acc = fmaf(es[e], wr[e], acc);
        g_embproj[bid * 128 + n] = acc;
    } else {
        const int n = bid - 512;
        const float* wr = (n < 64) ? (Wf + n * KDIM) : (Wb + (n - 64) * KDIM);
        #pragma unroll
        for (int k = tid; k < FEAT; k += 128)
            g_Wh[n * FEAT + k] = __float2half_rn(wr[k]);
    }
}

// ---------------------------------------------------------------------------
// Kernel 1: fp16 mma GEMM (M=32768, N=128, K=768), fp32 accumulate.
// 512 CTAs x 64 rows; 8 warps (4m x 2n; warp tile 16x64); K-chunk 64; dbuf.
// A: LDG fp32 (1 chunk ahead) -> cvt -> STS half.  B: cp.async from g_Wh.
// smem 55KB static -> 3 CTAs/SM.
// ---------------------------------------------------------------------------
#define GK    64
#define NCH   (FEAT / GK)    // 12
#define APAD  72             // halves per row (144B stride)

__global__ __launch_bounds__(256, 3)
void gemm1_kernel(const float* __restrict__ inp, const int* __restrict__ posi)
{
    __shared__ __half Asm[2][64 * APAD];
    __shared__ __half Bsm[2][128 * APAD];

    const int tid  = threadIdx.x;
    const int m0   = blockIdx.x * 64;
    const int lane = tid & 31;
    const int warp = tid >> 5;
    const int wm   = warp >> 1;      // 0..3 -> rows wm*16..+15
    const int wn   = warp & 1;       // 0..1 -> cols wn*64..+63
    const int g    = lane >> 2;
    const int t4   = lane & 3;

    bool p64;
    {
        int odd  = posi[2 * lane + 1];
        int even = posi[2 * lane];
        bool z = (odd == 0) && (even >= 0) && (even < 512);
        p64 = (__ballot_sync(0xffffffffu, z) == 0xffffffffu);
    }

    // A staging: 4 threads per row, 16 floats each
    const int ar = tid >> 2;             // row 0..63
    const int ac = (tid & 3) * 16;       // float col 0/16/32/48
    uint4 qa[2];

    auto ldgA = [&](int ch) {
        const float* p = inp + (size_t)(m0 + ar) * FEAT + ch * GK + ac;
        float4 v0 = __ldg((const float4*)(p + 0));
        float4 v1 = __ldg((const float4*)(p + 4));
        float4 v2 = __ldg((const float4*)(p + 8));
        float4 v3 = __ldg((const float4*)(p + 12));
        __half2 h[8];
        h[0] = __floats2half2_rn(v0.x, v0.y); h[1] = __floats2half2_rn(v0.z, v0.w);
        h[2] = __floats2half2_rn(v1.x, v1.y); h[3] = __floats2half2_rn(v1.z, v1.w);
        h[4] = __floats2half2_rn(v2.x, v2.y); h[5] = __floats2half2_rn(v2.z, v2.w);
        h[6] = __floats2half2_rn(v3.x, v3.y); h[7] = __floats2half2_rn(v3.z, v3.w);
        qa[0] = *(uint4*)&h[0];
        qa[1] = *(uint4*)&h[4];
    };
    auto stsA = [&](int s) {
        *(uint4*)&Asm[s][ar * APAD + ac]     = qa[0];
        *(uint4*)&Asm[s][ar * APAD + ac + 8] = qa[1];
    };
    auto stageB = [&](int ch, int s) {
        #pragma unroll
        for (int i = 0; i < 4; i++) {
            int lin = tid + i * 256;          // 1024 pieces of 8 halves
            int n = lin >> 3, c8 = lin & 7;
            cpa16(&Bsm[s][n * APAD + c8 * 8],
                  g_Wh + (size_t)n * FEAT + ch * GK + c8 * 8);
        }
    };

    float c[8][4];
    #pragma unroll
    for (int nt = 0; nt < 8; nt++)
        #pragma unroll
        for (int i = 0; i < 4; i++) c[nt][i] = 0.f;

    ldgA(0);
    stageB(0, 0);
    asm volatile("cp.async.commit_group;\n" ::: "memory");

    for (int ch = 0; ch < NCH; ch++) {
        const int s = ch & 1;
        stsA(s);                                        // A(ch) regs -> smem
        asm volatile("cp.async.wait_group 0;\n" ::: "memory");   // B(ch) landed
        __syncthreads();
        if (ch + 1 < NCH) {
            ldgA(ch + 1);                               // DRAM fetch in flight
            stageB(ch + 1, s ^ 1);
            asm volatile("cp.async.commit_group;\n" ::: "memory");
        }

        const __half* Ab = Asm[s];
        const __half* Bb = Bsm[s];
        #pragma unroll
        for (int ks = 0; ks < 4; ks++) {
            const int kb = ks * 16;
            uint32_t a[4], bb[8][2];
            {
                int base = (wm * 16 + g) * APAD + kb + t4 * 2;
                a[0] = *(const uint32_t*)&Ab[base];
                a[1] = *(const uint32_t*)&Ab[base + 8 * APAD];
                a[2] = *(const uint32_t*)&Ab[base + 8];
                a[3] = *(const uint32_t*)&Ab[base + 8 * APAD + 8];
            }
            #pragma unroll
            for (int nt = 0; nt < 8; nt++) {
                int cn = wn * 64 + nt * 8 + g;
                int bbase = cn * APAD + kb + t4 * 2;
                bb[nt][0] = *(const uint32_t*)&Bb[bbase];
                bb[nt][1] = *(const uint32_t*)&Bb[bbase + 8];
            }
            #pragma unroll
            for (int nt = 0; nt < 8; nt++)
                mma_f16(c[nt], a, bb[nt]);
        }
    }

    // epilogue: + embproj[pos[row]], store transposed to g_xp[dir][tok][64]
    {
        int r = m0 + wm * 16 + g;
        int i0 = (p64 ? posi[2 * r] : posi[r]) & 511;
        int i1 = (p64 ? posi[2 * (r + 8)] : posi[r + 8]) & 511;
        const float* e0 = g_embproj + i0 * 128;
        const float* e1 = g_embproj + i1 * 128;
        #pragma unroll
        for (int nt = 0; nt < 8; nt++) {
            int cn = wn * 64 + nt * 8 + 2 * t4;
            int dir = cn >> 6, j = cn & 63;
            size_t base0 = (size_t)dir * (NTOK * 64) + (size_t)r * 64 + j;
            size_t base1 = (size_t)dir * (NTOK * 64) + (size_t)(r + 8) * 64 + j;
            g_xp[base0]     = c[nt][0] + e0[cn];
            g_xp[base0 + 1] = c[nt][1] + e0[cn + 1];
            g_xp[base1]     = c[nt][2] + e1[cn];
            g_xp[base1 + 1] = c[nt][3] + e1[cn + 1];
        }
    }
}

// ---------------------------------------------------------------------------
// Kernel 2: RNN scans. 128 CTAs = (b,dir), 128 threads; pair-split dot;
// coalesced xp/h ([dir][b][t][64]); exact fast tanh via __expf.
// ---------------------------------------------------------------------------
__global__ __launch_bounds__(128, 8)
void scan_kernel(const float* __restrict__ Whf, const float* __restrict__ Whb)
{
    const int pair = blockIdx.x;
    const int b = pair >> 1, dir = pair & 1;
    const int tid  = threadIdx.x;
    const int j    = tid >> 1;
    const int half = tid & 1;

    const float* W = dir ? Whb : Whf;
    float w[32];
    #pragma unroll
    for (int k = 0; k < 32; k += 4) {
        float4 v = *(const float4*)(W + j * 64 + half * 32 + k);
        w[k] = v.x; w[k + 1] = v.y; w[k + 2] = v.z; w[k + 3] = v.w;
    }

    __shared__ float hbuf[2][64];
    if (tid < 64) hbuf[0][tid] = 0.f;
    __syncthreads();

    const size_t sbase = (size_t)dir * (NTOK * 64) + (size_t)b * (TT * 64) + j;
    const float* xpb = g_xp + sbase;
    float*       ob  = g_h  + sbase;

    float xq[4];
    #pragma unroll
    for (int i = 0; i < 4; i++) {
        int t = dir ? (TT - 1 - i) : i;
        xq[i] = __ldg(xpb + (size_t)t * 64);
    }

    int p = 0;
    for (int s4 = 0; s4 < TT / 4; s4++) {
        #pragma unroll
        for (int u = 0; u < 4; u++) {
            const int s = s4 * 4 + u;
            float x = xq[u];
            const int sp = s + 4;
            if (sp < TT) {
                int tp = dir ? (TT - 1 - sp) : sp;
                xq[u] = __ldg(xpb + (size_t)tp * 64);
            }
            float a0 = 0.f, a1 = 0.f, a2 = 0.f, a3 = 0.f;
            const float* hp = hbuf[p] + half * 32;
            #pragma unroll
            for (int k = 0; k < 32; k += 4) {
                float4 hv = *(const float4*)(hp + k);
                a0 = fmaf(w[k],     hv.x, a0);
                a1 = fmaf(w[k + 1], hv.y, a1);
                a2 = fmaf(w[k + 2], hv.z, a2);
                a3 = fmaf(w[k + 3], hv.w, a3);
            }
            float a = (a0 + a1) + (a2 + a3);
            a += __shfl_xor_sync(0xffffffffu, a, 1);
            float z = x + a;
            float e = __expf(z + z);
            float h = 1.f - __fdividef(2.f, e + 1.f);
            int t = dir ? (TT - 1 - s) : s;
            if (half == 0) hbuf[p ^ 1][j] = h;
            else           ob[(size_t)t * 64] = h;
            __syncthreads();
            p ^= 1;
        }
    }
}

// ---------------------------------------------------------------------------
// Kernel 3: head (128-token tiles, as measured at 20.6us), transposed g_h in.
// ---------------------------------------------------------------------------
#define HEAD_SMEM_FLOATS (128*132 + 128*36 + 128*33 + 128 + 32*3 + 4)

__global__ __launch_bounds__(256, 2)
void head_kernel(const float* __restrict__ W1, const float* __restrict__ b1,
                 const float* __restrict__ gamma, const float* __restrict__ beta,
                 const float* __restrict__ W2, const float* __restrict__ b2,
                 float* __restrict__ out)
{
    extern __shared__ float sm[];
    float* As  = sm;                    // [k][m]  128 x 132
    float* W1t = As + 128 * 132;        // [k][n]  128 x 36
    float* h1s = W1t + 128 * 36;        // [m][n]  128 x 33
    float* W2s = h1s + 128 * 33;        // 128
    float* b1s = W2s + 128;             // 32
    float* gms = b1s + 32;              // 32
    float* bts = gms + 32;              // 32
    float* b2s = bts + 32;              // 4

    const int tid = threadIdx.x;
    const int t0  = blockIdx.x * 128;

    #pragma unroll
    for (int i = 0; i < 16; i++) {      // W1t[k][n] = W1[n][k]
        int lin = tid + i * 256;
        int k = lin & 127, n = lin >> 7;
        W1t[k * 36 + n] = W1[n * 128 + k];
    }
    if (tid < 128) W2s[tid] = W2[tid];
    if (tid < 32) { b1s[tid] = b1[tid]; gms[tid] = gamma[tid]; bts[tid] = beta[tid]; }
    if (tid < 4)  b2s[tid] = b2[tid];

    // As[k][m] from transposed g_h: k<64 fwd, k>=64 bwd
    #pragma unroll
    for (int i = 0; i < 16; i++) {
        int lin = tid + i * 256;        // 4096 float4 pieces
        int m = lin & 127, k4 = lin >> 7;   // k4 0..31
        size_t src = (k4 >= 16 ? (size_t)(NTOK * 64) : 0)
                   + (size_t)(t0 + m) * 64 + (k4 & 15) * 4;
        float4 v = *(const float4*)(g_h + src);
        As[(k4 * 4 + 0) * 132 + m] = v.x;
        As[(k4 * 4 + 1) * 132 + m] = v.y;
        As[(k4 * 4 + 2) * 132 + m] = v.z;
        As[(k4 * 4 + 3) * 132 + m] = v.w;
    }
    __syncthreads();

    const int tt = tid >> 3;
    const int ot = tid & 7;
    float acc[4][4];
    #pragma unroll
    for (int i = 0; i < 4; i++)
        #pragma unroll
        for (int jx = 0; jx < 4; jx++) acc[i][jx] = 0.f;

    #pragma unroll 8
    for (int k = 0; k < 128; k++) {
        float4 av = *(const float4*)(As + k * 132 + tt * 4);
        float4 bv = *(const float4*)(W1t + k * 36 + ot * 4);
        acc[0][0] = fmaf(av.x, bv.x, acc[0][0]); acc[0][1] = fmaf(av.x, bv.y, acc[0][1]);
        acc[0][2] = fmaf(av.x, bv.z, acc[0][2]); acc[0][3] = fmaf(av.x, bv.w, acc[0][3]);
        acc[1][0] = fmaf(av.y, bv.x, acc[1][0]); acc[1][1] = fmaf(av.y, bv.y, acc[1][1]);
        acc[1][2] = fmaf(av.y, bv.z, acc[1][2]); acc[1][3] = fmaf(av.y, bv.w, acc[1][3]);
        acc[2][0] = fmaf(av.z, bv.x, acc[2][0]); acc[2][1] = fmaf(av.z, bv.y, acc[2][1]);
        acc[2][2] = fmaf(av.z, bv.z, acc[2][2]); acc[2][3] = fmaf(av.z, bv.w, acc[2][3]);
        acc[3][0] = fmaf(av.w, bv.x, acc[3][0]); acc[3][1] = fmaf(av.w, bv.y, acc[3][1]);
        acc[3][2] = fmaf(av.w, bv.z, acc[3][2]); acc[3][3] = fmaf(av.w, bv.w, acc[3][3]);
    }
    #pragma unroll
    for (int i = 0; i < 4; i++)
        #pragma unroll
        for (int jx = 0; jx < 4; jx++)
            h1s[(tt * 4 + i) * 33 + ot * 4 + jx] = acc[i][jx] + b1s[ot * 4 + jx];
    __syncthreads();

    if (tid < 128) {
        float h[32];
        #pragma unroll
        for (int i = 0; i < 32; i++) h[i] = h1s[tid * 33 + i];
        float s1 = 0.f, s2 = 0.f;
        #pragma unroll
        for (int i = 0; i < 32; i++) { s1 += h[i]; s2 = fmaf(h[i], h[i], s2); }
        float mu  = s1 * (1.f / 32.f);
        float var = s2 * (1.f / 32.f) - mu * mu;
        float inv = rsqrtf(var + 1e-5f);
        float o0 = b2s[0], o1 = b2s[1], o2 = b2s[2], o3 = b2s[3];
        #pragma unroll
        for (int i = 0; i < 32; i++) {
            float r = fmaf((h[i] - mu) * inv, gms[i], bts[i]);
            r = fmaxf(r, 0.f);
            o0 = fmaf(W2s[i],      r, o0);
            o1 = fmaf(W2s[32 + i], r, o1);
            o2 = fmaf(W2s[64 + i], r, o2);
            o3 = fmaf(W2s[96 + i], r, o3);
        }
        *(float4*)(out + (size_t)(t0 + tid) * 4) = make_float4(o0, o1, o2, o3);
    }
}

// ---------------------------------------------------------------------------
extern "C" void kernel_launch(void* const* d_in, const int* in_sizes, int n_in,
                              void* d_out, int out_size)
{
    const float* inputs = (const float*)d_in[0];
    const int*   posi   = (const int*)  d_in[1];
    const float* emb    = (const float*)d_in[2];
    const float* Wihf   = (const float*)d_in[3];
    const float* Whhf   = (const float*)d_in[4];
    const float* bihf   = (const float*)d_in[5];
    const float* bhhf   = (const float*)d_in[6];
    const float* Wihb   = (const float*)d_in[7];
    const float* Whhb   = (const float*)d_in[8];
    const float* bihb   = (const float*)d_in[9];
    const float* bhhb   = (const float*)d_in[10];
    const float* W1     = (const float*)d_in[11];
    const float* b1     = (const float*)d_in[12];
    const float* gamma  = (const float*)d_in[13];
    const float* beta   = (const float*)d_in[14];
    const float* W2     = (const float*)d_in[15];
    const float* b2     = (const float*)d_in[16];
    float* out = (float*)d_out;

    const int head_smem = HEAD_SMEM_FLOATS * (int)sizeof(float);
    cudaFuncSetAttribute(head_kernel, cudaFuncAttributeMaxDynamicSharedMemorySize, head_smem);

    prep_kernel<<<640, 128>>>(emb, Wihf, Wihb, bihf, bhhf, bihb, bhhb);
    gemm1_kernel<<<512, 256>>>(inputs, posi);
    scan_kernel<<<128, 128>>>(Whhf, Whhb);
    head_kernel<<<256, 256, head_smem>>>(W1, b1, gamma, beta, W2, b2, out);
}